// round 5
// baseline (speedup 1.0000x reference)
#include <cuda_runtime.h>
#include <cuda_bf16.h>
#include <math.h>

// ---------------- model constants ----------------
#define Vv 50257
#define VP 50304            // padded vocab (multiple of 128)
#define Dd 768
#define Hh 12
#define HD 64
#define Tt 1024
#define Ll 6
#define Bb 4
#define BT (Bb*Tt)          // 4096
#define FF (4*Dd)           // 3072

#define BM 128
#define BN 128
#define BKK 16
#define APAD 68             // attention smem row stride (floats)

// ---------------- scratch (static device arrays; no allocation) ----------------
__device__ float g_x   [BT*Dd];
__device__ float g_x2  [BT*Dd];
__device__ float g_q   [BT*Dd];
__device__ float g_k   [BT*Dd];
__device__ float g_v   [BT*Dd];
__device__ float g_y   [BT*Dd];
__device__ float g_ff1 [BT*FF];
__device__ float g_rl  [BT];
__device__ float g_wpad[(size_t)Dd*VP];   // padded, pre-tf32 head weights

__device__ __forceinline__ float to_tf32(float x) {
    float y;
    asm("cvt.rna.tf32.f32 %0, %1;" : "=f"(y) : "f"(x));
    return y;
}

// ---------------- embedding ----------------
__global__ void embed_kernel(const int* __restrict__ idx,
                             const float* __restrict__ tok,
                             const float* __restrict__ pos,
                             float* __restrict__ x) {
    int r = blockIdx.x;
    int t = r & (Tt - 1);
    int token = idx[r];
    const float* tr = tok + (size_t)token * Dd;
    const float* pr = pos + (size_t)t * Dd;
    float* xr = x + (size_t)r * Dd;
    for (int c = threadIdx.x; c < Dd; c += blockDim.x)
        xr[c] = tr[c] + pr[c];
}

// ---------------- pad + pre-convert head weights ----------------
__global__ void padw_kernel(const float* __restrict__ w, float* __restrict__ wp) {
    int kk = blockIdx.x;             // 0..767
    const float* src = w + (size_t)kk * Vv;
    float* dst = wp + (size_t)kk * VP;
    for (int n = threadIdx.x; n < VP; n += blockDim.x)
        dst[n] = (n < Vv) ? to_tf32(src[n]) : 0.f;
}

// ---------------- TF32 tensor-core GEMM core ----------------
// Paired-k smem layout: As2[k8][m][tig] = {A[k8*8+tig][m], A[k8*8+tig+4][m]}
// so fragment loads are LDS.64 instead of 2x LDS.32 (12 vs 24 LDS per k8-step).
// 256 threads = 8 warps (2M x 4N), warp tile 64x32, mma.m16n8k8.tf32.
template<int EPI>
__device__ __forceinline__ void gemm_core(
    const float* __restrict__ A, const float* __restrict__ Bm,
    const float* __restrict__ bias, float* __restrict__ C,
    int N, int K, int Bstride, int row0, int col0)
{
    __shared__ float2 As2[2][BM][4];   // 8 KB
    __shared__ float2 Bs2[2][BN][4];   // 8 KB

    int t    = threadIdx.x;
    int wid  = t >> 5;
    int lane = t & 31;
    int g    = lane >> 2;
    int tig  = lane & 3;
    int m0w  = (wid & 1) * 64;
    int n0w  = (wid >> 1) * 32;

    const bool vec_ok = ((col0 + BN) <= Bstride) && ((Bstride & 3) == 0);

    float acc[4][4][4];
#pragma unroll
    for (int im = 0; im < 4; im++)
#pragma unroll
        for (int in = 0; in < 4; in++)
#pragma unroll
            for (int c = 0; c < 4; c++) acc[im][in][c] = 0.f;

    for (int k0 = 0; k0 < K; k0 += BKK) {
        // ---- fill A: 128 rows x 16 k, 2 float4 per thread ----
#pragma unroll
        for (int i = 0; i < 2; i++) {
            int idx = t + i * 256;          // 0..511
            int row = idx >> 2;             // 0..127
            int seg = (idx & 3) * 4;        // 0,4,8,12
            float4 a4 = *(const float4*)(A + (size_t)(row0 + row) * K + k0 + seg);
            int k8   = seg >> 3;            // 0 or 1
            int half = (seg >> 2) & 1;      // .x or .y
            float* dstp = (float*)&As2[k8][row][0] + half;
            dstp[0] = to_tf32(a4.x);
            dstp[2] = to_tf32(a4.y);
            dstp[4] = to_tf32(a4.z);
            dstp[6] = to_tf32(a4.w);
        }
        // ---- fill B: 16 k x 128 n ----
        if (vec_ok) {
#pragma unroll
            for (int i = 0; i < 2; i++) {
                int idx = t + i * 256;      // 0..511
                int kr  = idx >> 5;         // 0..15
                int cs  = (idx & 31) * 4;   // 0..124
                float4 b4 = *(const float4*)(Bm + (size_t)(k0 + kr) * Bstride + col0 + cs);
                int k8   = kr >> 3;
                int tg   = kr & 3;
                int half = (kr >> 2) & 1;
                ((float*)&Bs2[k8][cs + 0][tg])[half] = to_tf32(b4.x);
                ((float*)&Bs2[k8][cs + 1][tg])[half] = to_tf32(b4.y);
                ((float*)&Bs2[k8][cs + 2][tg])[half] = to_tf32(b4.z);
                ((float*)&Bs2[k8][cs + 3][tg])[half] = to_tf32(b4.w);
            }
        } else {
#pragma unroll
            for (int i = 0; i < 8; i++) {
                int e = t + i * 256;        // 0..2047
                int kr = e >> 7, c = e & 127;
                int col = col0 + c;
                float vv = (col < Bstride) ? Bm[(size_t)(k0 + kr) * Bstride + col] : 0.f;
                int k8   = kr >> 3;
                int tg   = kr & 3;
                int half = (kr >> 2) & 1;
                ((float*)&Bs2[k8][c][tg])[half] = to_tf32(vv);
            }
        }
        __syncthreads();

        // ---- compute: 2 k8-steps x 16 MMAs ----
#pragma unroll
        for (int ks8 = 0; ks8 < 2; ks8++) {
            unsigned af[4][4], bf[4][2];
#pragma unroll
            for (int im = 0; im < 4; im++) {
                int m = m0w + im * 16 + g;
                float2 pa  = As2[ks8][m    ][tig];
                float2 pa8 = As2[ks8][m + 8][tig];
                af[im][0] = __float_as_uint(pa.x);
                af[im][1] = __float_as_uint(pa8.x);
                af[im][2] = __float_as_uint(pa.y);
                af[im][3] = __float_as_uint(pa8.y);
            }
#pragma unroll
            for (int in = 0; in < 4; in++) {
                int n = n0w + in * 8 + g;
                float2 pb = Bs2[ks8][n][tig];
                bf[in][0] = __float_as_uint(pb.x);
                bf[in][1] = __float_as_uint(pb.y);
            }
#pragma unroll
            for (int im = 0; im < 4; im++)
#pragma unroll
                for (int in = 0; in < 4; in++) {
                    asm volatile(
                        "mma.sync.aligned.m16n8k8.row.col.f32.tf32.tf32.f32 "
                        "{%0,%1,%2,%3},{%4,%5,%6,%7},{%8,%9},{%0,%1,%2,%3};"
                        : "+f"(acc[im][in][0]), "+f"(acc[im][in][1]),
                          "+f"(acc[im][in][2]), "+f"(acc[im][in][3])
                        : "r"(af[im][0]), "r"(af[im][1]), "r"(af[im][2]), "r"(af[im][3]),
                          "r"(bf[in][0]), "r"(bf[in][1]));
                }
        }
        __syncthreads();
    }

    // ---- epilogue ----
#pragma unroll
    for (int im = 0; im < 4; im++) {
        int r_lo = row0 + m0w + im * 16 + g;
        int r_hi = r_lo + 8;
#pragma unroll
        for (int in = 0; in < 4; in++) {
            int c_lo = col0 + n0w + in * 8 + 2 * tig;
            int c_hi = c_lo + 1;
            float v0 = acc[im][in][0], v1 = acc[im][in][1];
            float v2 = acc[im][in][2], v3 = acc[im][in][3];
            if (EPI >= 1) {
                if (c_lo < N) { v0 += bias[c_lo]; v2 += bias[c_lo]; }
                if (c_hi < N) { v1 += bias[c_hi]; v3 += bias[c_hi]; }
            }
            if (EPI == 2) {
                v0 = fmaxf(v0, 0.f); v1 = fmaxf(v1, 0.f);
                v2 = fmaxf(v2, 0.f); v3 = fmaxf(v3, 0.f);
            }
            size_t blo = (size_t)r_lo * N;
            size_t bhi = (size_t)r_hi * N;
            if (c_lo < N) { C[blo + c_lo] = v0; C[bhi + c_lo] = v2; }
            if (c_hi < N) { C[blo + c_hi] = v1; C[bhi + c_hi] = v3; }
        }
    }
}

template<int EPI>
__global__ __launch_bounds__(256)
void tgemm_kernel(const float* __restrict__ A, const float* __restrict__ Bm,
                  const float* __restrict__ bias, float* __restrict__ C,
                  int N, int K, int Bstride) {
    gemm_core<EPI>(A, Bm, bias, C, N, K, Bstride,
                   blockIdx.y * BM, blockIdx.x * BN);
}

// fused QKV: grid (18, 32); blockIdx.x selects {Wq,Wk,Wv} x 6 col-tiles
__global__ __launch_bounds__(256)
void qkv_kernel(const float* __restrict__ x,
                const float* __restrict__ wq, const float* __restrict__ wk,
                const float* __restrict__ wv,
                float* __restrict__ q, float* __restrict__ k, float* __restrict__ v) {
    int ct  = blockIdx.x;          // 0..17
    int mat = ct / 6;
    int c   = ct % 6;
    const float* B = (mat == 0) ? wq : (mat == 1) ? wk : wv;
    float*       C = (mat == 0) ? q  : (mat == 1) ? k  : v;
    gemm_core<0>(x, B, nullptr, C, Dd, Dd, Dd, blockIdx.y * BM, c * BN);
}

// ---------------- causal flash attention v2 ----------------
// grid (T/64, H, B), 256 threads. 64-query x 64-key tiles, register 4x4 microtiles.
// dynamic smem: Qs,Ks,Vs,Ss [64][APAD] + mrow/lrow/cfac[64]
#define ATTN_SMEM ((4*64*APAD + 3*64) * 4)
__global__ __launch_bounds__(256)
void attn_kernel(const float* __restrict__ q, const float* __restrict__ k,
                 const float* __restrict__ v, float* __restrict__ y) {
    extern __shared__ float asmem[];
    float* Qs   = asmem;
    float* Ks   = Qs + 64 * APAD;
    float* Vs   = Ks + 64 * APAD;
    float* Ss   = Vs + 64 * APAD;
    float* mrow = Ss + 64 * APAD;
    float* lrow = mrow + 64;
    float* cfac = lrow + 64;

    int t  = threadIdx.x;
    int q0 = blockIdx.x * 64;
    int h  = blockIdx.y;
    int b  = blockIdx.z;

    // load Q tile (64x64 floats, float4)
    for (int i = t; i < 64 * 16; i += 256) {
        int r = i >> 4, c4 = i & 15;
        *(float4*)(Qs + r * APAD + c4 * 4) =
            *(const float4*)(q + ((size_t)(b * Tt + q0 + r)) * Dd + h * HD + c4 * 4);
    }
    if (t < 64) { mrow[t] = -1e30f; lrow[t] = 0.f; }

    int qg  = t >> 4;          // 0..15
    int qi0 = qg * 4;
    int kb  = t & 15;          // score: kj = kb + 16*jj;  PV/out: d = kb*4+dc

    float acc[4][4];
#pragma unroll
    for (int i = 0; i < 4; i++)
#pragma unroll
        for (int dc = 0; dc < 4; dc++) acc[i][dc] = 0.f;

    int ntiles = blockIdx.x + 1;
    __syncthreads();

    for (int jt = 0; jt < ntiles; jt++) {
        int s0 = jt * 64;
        // load K,V tiles
        for (int i = t; i < 64 * 16; i += 256) {
            int r = i >> 4, c4 = i & 15;
            size_t gb = ((size_t)(b * Tt + s0 + r)) * Dd + h * HD + c4 * 4;
            *(float4*)(Ks + r * APAD + c4 * 4) = *(const float4*)(k + gb);
            *(float4*)(Vs + r * APAD + c4 * 4) = *(const float4*)(v + gb);
        }
        __syncthreads();

        // scores: s[4 qi][4 kj], kj = kb + 16*jj
        float s[4][4];
#pragma unroll
        for (int i = 0; i < 4; i++)
#pragma unroll
            for (int jj = 0; jj < 4; jj++) s[i][jj] = 0.f;
#pragma unroll
        for (int c = 0; c < 16; c++) {
            float4 qv[4], kv[4];
#pragma unroll
            for (int i = 0; i < 4; i++)
                qv[i] = *(float4*)(Qs + (qi0 + i) * APAD + c * 4);
#pragma unroll
            for (int jj = 0; jj < 4; jj++)
                kv[jj] = *(float4*)(Ks + (kb + 16 * jj) * APAD + c * 4);
#pragma unroll
            for (int i = 0; i < 4; i++)
#pragma unroll
                for (int jj = 0; jj < 4; jj++)
                    s[i][jj] += qv[i].x * kv[jj].x + qv[i].y * kv[jj].y
                              + qv[i].z * kv[jj].z + qv[i].w * kv[jj].w;
        }
#pragma unroll
        for (int i = 0; i < 4; i++)
#pragma unroll
            for (int jj = 0; jj < 4; jj++) {
                int qi = qi0 + i, kj = kb + 16 * jj;
                float val = s[i][jj] * 0.125f;
                if (s0 + kj > q0 + qi) val = -1e30f;
                Ss[qi * APAD + kj] = val;
            }
        __syncthreads();

        // online softmax: thread t<64 owns row t
        if (t < 64) {
            float m = mrow[t], nm = m;
            float* srow = Ss + t * APAD;
#pragma unroll 8
            for (int kj = 0; kj < 64; kj++) nm = fmaxf(nm, srow[kj]);
            float corr = __expf(m - nm);
            float sum = 0.f;
#pragma unroll 8
            for (int kj = 0; kj < 64; kj++) {
                float p = __expf(srow[kj] - nm);
                srow[kj] = p;
                sum += p;
            }
            lrow[t] = lrow[t] * corr + sum;
            mrow[t] = nm;
            cfac[t] = corr;
        }
        __syncthreads();

        // rescale + P@V
#pragma unroll
        for (int i = 0; i < 4; i++) {
            float corr = cfac[qi0 + i];
#pragma unroll
            for (int dc = 0; dc < 4; dc++) acc[i][dc] *= corr;
        }
#pragma unroll
        for (int kc = 0; kc < 16; kc++) {
            float4 pv[4], vv[4];
#pragma unroll
            for (int i = 0; i < 4; i++)
                pv[i] = *(float4*)(Ss + (qi0 + i) * APAD + kc * 4);
#pragma unroll
            for (int jj = 0; jj < 4; jj++)
                vv[jj] = *(float4*)(Vs + (kc * 4 + jj) * APAD + kb * 4);
#pragma unroll
            for (int i = 0; i < 4; i++) {
                acc[i][0] += pv[i].x * vv[0].x + pv[i].y * vv[1].x + pv[i].z * vv[2].x + pv[i].w * vv[3].x;
                acc[i][1] += pv[i].x * vv[0].y + pv[i].y * vv[1].y + pv[i].z * vv[2].y + pv[i].w * vv[3].y;
                acc[i][2] += pv[i].x * vv[0].z + pv[i].y * vv[1].z + pv[i].z * vv[2].z + pv[i].w * vv[3].z;
                acc[i][3] += pv[i].x * vv[0].w + pv[i].y * vv[1].w + pv[i].z * vv[2].w + pv[i].w * vv[3].w;
            }
        }
        __syncthreads();
    }

    // normalize + store
#pragma unroll
    for (int i = 0; i < 4; i++) {
        float inv = 1.f / lrow[qi0 + i];
        float4 o;
        o.x = acc[i][0] * inv; o.y = acc[i][1] * inv;
        o.z = acc[i][2] * inv; o.w = acc[i][3] * inv;
        *(float4*)(y + ((size_t)(b * Tt + q0 + qi0 + i)) * Dd + h * HD + kb * 4) = o;
    }
}

// ---------------- residual + LayerNorm ----------------
__global__ __launch_bounds__(256)
void ln_res_kernel(const float* __restrict__ a, const float* __restrict__ b,
                   const float* __restrict__ g, const float* __restrict__ be,
                   float* __restrict__ out) {
    __shared__ float buf[Dd];
    __shared__ float red[256];
    int r = blockIdx.x;
    int t = threadIdx.x;
    const float* ar = a + (size_t)r * Dd;
    const float* br = b + (size_t)r * Dd;

    float s = 0.f;
    for (int c = t; c < Dd; c += 256) {
        float vv = ar[c] + br[c];
        buf[c] = vv;
        s += vv;
    }
    red[t] = s; __syncthreads();
    for (int o = 128; o > 0; o >>= 1) { if (t < o) red[t] += red[t + o]; __syncthreads(); }
    float mu = red[0] / (float)Dd;
    __syncthreads();

    float s2 = 0.f;
    for (int c = t; c < Dd; c += 256) {
        float d = buf[c] - mu;
        s2 += d * d;
    }
    red[t] = s2; __syncthreads();
    for (int o = 128; o > 0; o >>= 1) { if (t < o) red[t] += red[t + o]; __syncthreads(); }
    float rstd = rsqrtf(red[0] / (float)Dd + 1e-5f);

    float* orr = out + (size_t)r * Dd;
    for (int c = t; c < Dd; c += 256)
        orr[c] = (buf[c] - mu) * rstd * g[c] + be[c];
}

// ---------------- per-row cross-entropy ----------------
__global__ __launch_bounds__(256)
void rowloss_kernel(const float* __restrict__ logits, const int* __restrict__ tgt,
                    float* __restrict__ rl) {
    __shared__ float sm[256], sl[256];
    int r = blockIdx.x;
    int t = threadIdx.x;
    const float* lg = logits + (size_t)r * Vv;

    float m = -1e30f, l = 0.f;
    for (int c = t; c < Vv; c += 256) {
        float x = lg[c];
        if (x > m) { l = l * __expf(m - x) + 1.f; m = x; }
        else       { l += __expf(x - m); }
    }
    sm[t] = m; sl[t] = l; __syncthreads();
    for (int o = 128; o > 0; o >>= 1) {
        if (t < o) {
            float m1 = sm[t], m2 = sm[t + o];
            float M = fmaxf(m1, m2);
            sl[t] = sl[t] * __expf(m1 - M) + sl[t + o] * __expf(m2 - M);
            sm[t] = M;
        }
        __syncthreads();
    }
    if (t == 0)
        rl[r] = (sm[0] + logf(sl[0])) - lg[tgt[r]];
}

__global__ __launch_bounds__(256)
void meanloss_kernel(const float* __restrict__ rl, float* __restrict__ out) {
    __shared__ float red[256];
    int t = threadIdx.x;
    float s = 0.f;
    for (int i = t; i < BT; i += 256) s += rl[i];
    red[t] = s; __syncthreads();
    for (int o = 128; o > 0; o >>= 1) { if (t < o) red[t] += red[t + o]; __syncthreads(); }
    if (t == 0) out[0] = red[0] / (float)BT;
}

// ---------------- launch ----------------
extern "C" void kernel_launch(void* const* d_in, const int* in_sizes, int n_in,
                              void* d_out, int out_size) {
    const int*   idx    = (const int*)  d_in[0];
    const int*   tgt    = (const int*)  d_in[1];
    const float* tok    = (const float*)d_in[2];
    const float* pos    = (const float*)d_in[3];
    const float* Wq     = (const float*)d_in[4];
    const float* Wk     = (const float*)d_in[5];
    const float* Wv     = (const float*)d_in[6];
    const float* ln1g   = (const float*)d_in[7];
    const float* ln1b   = (const float*)d_in[8];
    const float* W1     = (const float*)d_in[9];
    const float* b1     = (const float*)d_in[10];
    const float* W2     = (const float*)d_in[11];
    const float* b2     = (const float*)d_in[12];
    const float* ln2g   = (const float*)d_in[13];
    const float* ln2b   = (const float*)d_in[14];
    const float* headw  = (const float*)d_in[15];
    const float* headb  = (const float*)d_in[16];
    float* out = (float*)d_out;

    float *x, *x2, *q, *k, *v, *y, *ff1, *rl, *wpad;
    cudaGetSymbolAddress((void**)&x,    g_x);
    cudaGetSymbolAddress((void**)&x2,   g_x2);
    cudaGetSymbolAddress((void**)&q,    g_q);
    cudaGetSymbolAddress((void**)&k,    g_k);
    cudaGetSymbolAddress((void**)&v,    g_v);
    cudaGetSymbolAddress((void**)&y,    g_y);
    cudaGetSymbolAddress((void**)&ff1,  g_ff1);
    cudaGetSymbolAddress((void**)&rl,   g_rl);
    cudaGetSymbolAddress((void**)&wpad, g_wpad);

    cudaFuncSetAttribute(attn_kernel,
                         cudaFuncAttributeMaxDynamicSharedMemorySize, ATTN_SMEM);

    embed_kernel<<<BT, 256>>>(idx, tok, pos, x);
    padw_kernel<<<Dd, 256>>>(headw, wpad);

    dim3 gQKV(18, BT / 128);
    dim3 gD(Dd / 128, BT / 128);             // 6 x 32
    dim3 gF(FF / 128, BT / 128);             // 24 x 32
    dim3 gV(VP / 128, BT / 128);             // 393 x 32

    for (int l = 0; l < Ll; l++) {
        const float* wq = Wq + (size_t)l * Dd * Dd;
        const float* wk = Wk + (size_t)l * Dd * Dd;
        const float* wv = Wv + (size_t)l * Dd * Dd;
        const float* w1 = W1 + (size_t)l * Dd * FF;
        const float* w2 = W2 + (size_t)l * FF * Dd;

        qkv_kernel<<<gQKV, 256>>>(x, wq, wk, wv, q, k, v);

        attn_kernel<<<dim3(Tt / 64, Hh, Bb), 256, ATTN_SMEM>>>(q, k, v, y);

        ln_res_kernel<<<BT, 256>>>(y, x, ln1g + l * Dd, ln1b + l * Dd, x2);

        tgemm_kernel<2><<<gF, 256>>>(x2, w1, b1 + (size_t)l * FF, ff1, FF, Dd, FF);
        tgemm_kernel<1><<<gD, 256>>>(ff1, w2, b2 + (size_t)l * Dd, y, Dd, FF, Dd);

        ln_res_kernel<<<BT, 256>>>(y, x2, ln2g + l * Dd, ln2b + l * Dd, x);
    }

    // head: padded, pre-converted B with stride VP; stores guarded to N=Vv
    tgemm_kernel<1><<<gV, 256>>>(x, wpad, headb, out, Vv, Dd, VP);

    rowloss_kernel<<<BT, 256>>>(out, tgt, rl);
    meanloss_kernel<<<1, 256>>>(rl, out + (size_t)BT * Vv);
}

// round 6
// speedup vs baseline: 1.8669x; 1.8669x over previous
#include <cuda_runtime.h>
#include <cuda_bf16.h>
#include <math.h>

// ---------------- model constants ----------------
#define Vv 50257
#define VP 50304            // padded vocab (multiple of 128)
#define Dd 768
#define Hh 12
#define HD 64
#define Tt 1024
#define Ll 6
#define Bb 4
#define BT (Bb*Tt)          // 4096
#define FF (4*Dd)           // 3072

#define BM 128
#define BN 128
#define BKK 16
#define APAD 68             // attention smem row stride (floats)

// ---------------- scratch (static device arrays; no allocation) ----------------
__device__ float g_x   [BT*Dd];
__device__ float g_x2  [BT*Dd];
__device__ float g_q   [BT*Dd];
__device__ float g_k   [BT*Dd];
__device__ float g_v   [BT*Dd];
__device__ float g_y   [BT*Dd];
__device__ float g_ff1 [BT*FF];
__device__ float g_rl  [BT];
__device__ float g_wpad[(size_t)Dd*VP];   // padded, pre-tf32 head weights

__device__ __forceinline__ float to_tf32(float x) {
    float y;
    asm("cvt.rna.tf32.f32 %0, %1;" : "=f"(y) : "f"(x));
    return y;
}

// ---------------- embedding ----------------
__global__ void embed_kernel(const int* __restrict__ idx,
                             const float* __restrict__ tok,
                             const float* __restrict__ pos,
                             float* __restrict__ x) {
    int r = blockIdx.x;
    int t = r & (Tt - 1);
    int token = idx[r];
    const float* tr = tok + (size_t)token * Dd;
    const float* pr = pos + (size_t)t * Dd;
    float* xr = x + (size_t)r * Dd;
    for (int c = threadIdx.x; c < Dd; c += blockDim.x)
        xr[c] = tr[c] + pr[c];
}

// ---------------- pad + pre-convert head weights ----------------
__global__ void padw_kernel(const float* __restrict__ w, float* __restrict__ wp) {
    int kk = blockIdx.x;             // 0..767
    const float* src = w + (size_t)kk * Vv;
    float* dst = wp + (size_t)kk * VP;
    for (int n = threadIdx.x; n < VP; n += blockDim.x)
        dst[n] = (n < Vv) ? to_tf32(src[n]) : 0.f;
}

// ---------------- TF32 tensor-core GEMM core (R3-verified mainloop) ----------------
// BM=128, BN=128, BK=16. 256 threads = 8 warps (2M x 4N), warp tile 64x32,
// mma.m16n8k8.tf32. One fill + one sync pair per k-tile.
template<int EPI>
__device__ __forceinline__ void gemm_core(
    const float* __restrict__ A, const float* __restrict__ Bm,
    const float* __restrict__ bias, float* __restrict__ C,
    int N, int K, int Bstride, int row0, int col0)
{
    __shared__ float As[BKK][BM + 4];   // As[k][m]
    __shared__ float Bs[BKK][BN + 4];   // Bs[k][n]

    int t    = threadIdx.x;
    int wid  = t >> 5;
    int lane = t & 31;
    int g    = lane >> 2;
    int tig  = lane & 3;
    int m0w  = (wid & 1) * 64;
    int n0w  = (wid >> 1) * 32;

    const bool vec_ok = ((col0 + BN) <= Bstride) && ((Bstride & 3) == 0);

    float acc[4][4][4];
#pragma unroll
    for (int im = 0; im < 4; im++)
#pragma unroll
        for (int in = 0; in < 4; in++)
#pragma unroll
            for (int c = 0; c < 4; c++) acc[im][in][c] = 0.f;

    for (int k0 = 0; k0 < K; k0 += BKK) {
        // ---- load A tile: 128x16, float4 per thread x2, transpose to As[k][m] ----
#pragma unroll
        for (int i = 0; i < 2; i++) {
            int idx = t + i * 256;          // 0..511
            int row = idx >> 2;             // 0..127
            int seg = (idx & 3) * 4;        // 0,4,8,12
            float4 a4 = *(const float4*)(A + (size_t)(row0 + row) * K + k0 + seg);
            As[seg + 0][row] = to_tf32(a4.x);
            As[seg + 1][row] = to_tf32(a4.y);
            As[seg + 2][row] = to_tf32(a4.z);
            As[seg + 3][row] = to_tf32(a4.w);
        }
        // ---- load B tile: 16x128 ----
        if (vec_ok) {
#pragma unroll
            for (int i = 0; i < 2; i++) {
                int idx = t + i * 256;      // 0..511
                int kr  = idx >> 5;         // 0..15
                int cs  = (idx & 31) * 4;   // 0..124
                float4 b4 = *(const float4*)(Bm + (size_t)(k0 + kr) * Bstride + col0 + cs);
                Bs[kr][cs + 0] = to_tf32(b4.x);
                Bs[kr][cs + 1] = to_tf32(b4.y);
                Bs[kr][cs + 2] = to_tf32(b4.z);
                Bs[kr][cs + 3] = to_tf32(b4.w);
            }
        } else {
#pragma unroll
            for (int i = 0; i < 8; i++) {
                int e = t + i * 256;        // 0..2047
                int kr = e >> 7;            // 0..15
                int c  = e & 127;
                int col = col0 + c;
                Bs[kr][c] = (col < Bstride) ? to_tf32(Bm[(size_t)(k0 + kr) * Bstride + col]) : 0.f;
            }
        }
        __syncthreads();

#pragma unroll
        for (int ks = 0; ks < BKK; ks += 8) {
            unsigned af[4][4], bf[4][2];
#pragma unroll
            for (int im = 0; im < 4; im++) {
                int m = m0w + im * 16 + g;
                af[im][0] = __float_as_uint(As[ks + tig    ][m    ]);
                af[im][1] = __float_as_uint(As[ks + tig    ][m + 8]);
                af[im][2] = __float_as_uint(As[ks + tig + 4][m    ]);
                af[im][3] = __float_as_uint(As[ks + tig + 4][m + 8]);
            }
#pragma unroll
            for (int in = 0; in < 4; in++) {
                int n = n0w + in * 8 + g;
                bf[in][0] = __float_as_uint(Bs[ks + tig    ][n]);
                bf[in][1] = __float_as_uint(Bs[ks + tig + 4][n]);
            }
#pragma unroll
            for (int im = 0; im < 4; im++)
#pragma unroll
                for (int in = 0; in < 4; in++) {
                    asm volatile(
                        "mma.sync.aligned.m16n8k8.row.col.f32.tf32.tf32.f32 "
                        "{%0,%1,%2,%3},{%4,%5,%6,%7},{%8,%9},{%0,%1,%2,%3};"
                        : "+f"(acc[im][in][0]), "+f"(acc[im][in][1]),
                          "+f"(acc[im][in][2]), "+f"(acc[im][in][3])
                        : "r"(af[im][0]), "r"(af[im][1]), "r"(af[im][2]), "r"(af[im][3]),
                          "r"(bf[in][0]), "r"(bf[in][1]));
                }
        }
        __syncthreads();
    }

    // ---- epilogue ----
#pragma unroll
    for (int im = 0; im < 4; im++) {
        int r_lo = row0 + m0w + im * 16 + g;
        int r_hi = r_lo + 8;
#pragma unroll
        for (int in = 0; in < 4; in++) {
            int c_lo = col0 + n0w + in * 8 + 2 * tig;
            int c_hi = c_lo + 1;
            float v0 = acc[im][in][0], v1 = acc[im][in][1];
            float v2 = acc[im][in][2], v3 = acc[im][in][3];
            if (EPI >= 1) {
                if (c_lo < N) { v0 += bias[c_lo]; v2 += bias[c_lo]; }
                if (c_hi < N) { v1 += bias[c_hi]; v3 += bias[c_hi]; }
            }
            if (EPI == 2) {
                v0 = fmaxf(v0, 0.f); v1 = fmaxf(v1, 0.f);
                v2 = fmaxf(v2, 0.f); v3 = fmaxf(v3, 0.f);
            }
            size_t blo = (size_t)r_lo * N;
            size_t bhi = (size_t)r_hi * N;
            if (c_lo < N) { C[blo + c_lo] = v0; C[bhi + c_lo] = v2; }
            if (c_hi < N) { C[blo + c_hi] = v1; C[bhi + c_hi] = v3; }
        }
    }
}

template<int EPI>
__global__ __launch_bounds__(256)
void tgemm_kernel(const float* __restrict__ A, const float* __restrict__ Bm,
                  const float* __restrict__ bias, float* __restrict__ C,
                  int N, int K, int Bstride) {
    gemm_core<EPI>(A, Bm, bias, C, N, K, Bstride,
                   blockIdx.y * BM, blockIdx.x * BN);
}

// fused QKV: grid (18, 32); blockIdx.x selects {Wq,Wk,Wv} x 6 col-tiles
__global__ __launch_bounds__(256)
void qkv_kernel(const float* __restrict__ x,
                const float* __restrict__ wq, const float* __restrict__ wk,
                const float* __restrict__ wv,
                float* __restrict__ q, float* __restrict__ k, float* __restrict__ v) {
    int ct  = blockIdx.x;          // 0..17
    int mat = ct / 6;
    int c   = ct % 6;
    const float* B = (mat == 0) ? wq : (mat == 1) ? wk : wv;
    float*       C = (mat == 0) ? q  : (mat == 1) ? k  : v;
    gemm_core<0>(x, B, nullptr, C, Dd, Dd, Dd, blockIdx.y * BM, c * BN);
}

// ---------------- causal flash attention (R5-verified) ----------------
#define ATTN_SMEM ((4*64*APAD + 3*64) * 4)
__global__ __launch_bounds__(256)
void attn_kernel(const float* __restrict__ q, const float* __restrict__ k,
                 const float* __restrict__ v, float* __restrict__ y) {
    extern __shared__ float asmem[];
    float* Qs   = asmem;
    float* Ks   = Qs + 64 * APAD;
    float* Vs   = Ks + 64 * APAD;
    float* Ss   = Vs + 64 * APAD;
    float* mrow = Ss + 64 * APAD;
    float* lrow = mrow + 64;
    float* cfac = lrow + 64;

    int t  = threadIdx.x;
    int q0 = blockIdx.x * 64;
    int h  = blockIdx.y;
    int b  = blockIdx.z;

    for (int i = t; i < 64 * 16; i += 256) {
        int r = i >> 4, c4 = i & 15;
        *(float4*)(Qs + r * APAD + c4 * 4) =
            *(const float4*)(q + ((size_t)(b * Tt + q0 + r)) * Dd + h * HD + c4 * 4);
    }
    if (t < 64) { mrow[t] = -1e30f; lrow[t] = 0.f; }

    int qg  = t >> 4;
    int qi0 = qg * 4;
    int kb  = t & 15;

    float acc[4][4];
#pragma unroll
    for (int i = 0; i < 4; i++)
#pragma unroll
        for (int dc = 0; dc < 4; dc++) acc[i][dc] = 0.f;

    int ntiles = blockIdx.x + 1;
    __syncthreads();

    for (int jt = 0; jt < ntiles; jt++) {
        int s0 = jt * 64;
        for (int i = t; i < 64 * 16; i += 256) {
            int r = i >> 4, c4 = i & 15;
            size_t gb = ((size_t)(b * Tt + s0 + r)) * Dd + h * HD + c4 * 4;
            *(float4*)(Ks + r * APAD + c4 * 4) = *(const float4*)(k + gb);
            *(float4*)(Vs + r * APAD + c4 * 4) = *(const float4*)(v + gb);
        }
        __syncthreads();

        float s[4][4];
#pragma unroll
        for (int i = 0; i < 4; i++)
#pragma unroll
            for (int jj = 0; jj < 4; jj++) s[i][jj] = 0.f;
#pragma unroll
        for (int c = 0; c < 16; c++) {
            float4 qv[4], kv[4];
#pragma unroll
            for (int i = 0; i < 4; i++)
                qv[i] = *(float4*)(Qs + (qi0 + i) * APAD + c * 4);
#pragma unroll
            for (int jj = 0; jj < 4; jj++)
                kv[jj] = *(float4*)(Ks + (kb + 16 * jj) * APAD + c * 4);
#pragma unroll
            for (int i = 0; i < 4; i++)
#pragma unroll
                for (int jj = 0; jj < 4; jj++)
                    s[i][jj] += qv[i].x * kv[jj].x + qv[i].y * kv[jj].y
                              + qv[i].z * kv[jj].z + qv[i].w * kv[jj].w;
        }
#pragma unroll
        for (int i = 0; i < 4; i++)
#pragma unroll
            for (int jj = 0; jj < 4; jj++) {
                int qi = qi0 + i, kj = kb + 16 * jj;
                float val = s[i][jj] * 0.125f;
                if (s0 + kj > q0 + qi) val = -1e30f;
                Ss[qi * APAD + kj] = val;
            }
        __syncthreads();

        if (t < 64) {
            float m = mrow[t], nm = m;
            float* srow = Ss + t * APAD;
#pragma unroll 8
            for (int kj = 0; kj < 64; kj++) nm = fmaxf(nm, srow[kj]);
            float corr = __expf(m - nm);
            float sum = 0.f;
#pragma unroll 8
            for (int kj = 0; kj < 64; kj++) {
                float p = __expf(srow[kj] - nm);
                srow[kj] = p;
                sum += p;
            }
            lrow[t] = lrow[t] * corr + sum;
            mrow[t] = nm;
            cfac[t] = corr;
        }
        __syncthreads();

#pragma unroll
        for (int i = 0; i < 4; i++) {
            float corr = cfac[qi0 + i];
#pragma unroll
            for (int dc = 0; dc < 4; dc++) acc[i][dc] *= corr;
        }
#pragma unroll
        for (int kc = 0; kc < 16; kc++) {
            float4 pv[4], vv[4];
#pragma unroll
            for (int i = 0; i < 4; i++)
                pv[i] = *(float4*)(Ss + (qi0 + i) * APAD + kc * 4);
#pragma unroll
            for (int jj = 0; jj < 4; jj++)
                vv[jj] = *(float4*)(Vs + (kc * 4 + jj) * APAD + kb * 4);
#pragma unroll
            for (int i = 0; i < 4; i++) {
                acc[i][0] += pv[i].x * vv[0].x + pv[i].y * vv[1].x + pv[i].z * vv[2].x + pv[i].w * vv[3].x;
                acc[i][1] += pv[i].x * vv[0].y + pv[i].y * vv[1].y + pv[i].z * vv[2].y + pv[i].w * vv[3].y;
                acc[i][2] += pv[i].x * vv[0].z + pv[i].y * vv[1].z + pv[i].z * vv[2].z + pv[i].w * vv[3].z;
                acc[i][3] += pv[i].x * vv[0].w + pv[i].y * vv[1].w + pv[i].z * vv[2].w + pv[i].w * vv[3].w;
            }
        }
        __syncthreads();
    }

#pragma unroll
    for (int i = 0; i < 4; i++) {
        float inv = 1.f / lrow[qi0 + i];
        float4 o;
        o.x = acc[i][0] * inv; o.y = acc[i][1] * inv;
        o.z = acc[i][2] * inv; o.w = acc[i][3] * inv;
        *(float4*)(y + ((size_t)(b * Tt + q0 + qi0 + i)) * Dd + h * HD + kb * 4) = o;
    }
}

// ---------------- residual + LayerNorm ----------------
__global__ __launch_bounds__(256)
void ln_res_kernel(const float* __restrict__ a, const float* __restrict__ b,
                   const float* __restrict__ g, const float* __restrict__ be,
                   float* __restrict__ out) {
    __shared__ float buf[Dd];
    __shared__ float red[256];
    int r = blockIdx.x;
    int t = threadIdx.x;
    const float* ar = a + (size_t)r * Dd;
    const float* br = b + (size_t)r * Dd;

    float s = 0.f;
    for (int c = t; c < Dd; c += 256) {
        float vv = ar[c] + br[c];
        buf[c] = vv;
        s += vv;
    }
    red[t] = s; __syncthreads();
    for (int o = 128; o > 0; o >>= 1) { if (t < o) red[t] += red[t + o]; __syncthreads(); }
    float mu = red[0] / (float)Dd;
    __syncthreads();

    float s2 = 0.f;
    for (int c = t; c < Dd; c += 256) {
        float d = buf[c] - mu;
        s2 += d * d;
    }
    red[t] = s2; __syncthreads();
    for (int o = 128; o > 0; o >>= 1) { if (t < o) red[t] += red[t + o]; __syncthreads(); }
    float rstd = rsqrtf(red[0] / (float)Dd + 1e-5f);

    float* orr = out + (size_t)r * Dd;
    for (int c = t; c < Dd; c += 256)
        orr[c] = (buf[c] - mu) * rstd * g[c] + be[c];
}

// ---------------- per-row cross-entropy ----------------
__global__ __launch_bounds__(256)
void rowloss_kernel(const float* __restrict__ logits, const int* __restrict__ tgt,
                    float* __restrict__ rl) {
    __shared__ float sm[256], sl[256];
    int r = blockIdx.x;
    int t = threadIdx.x;
    const float* lg = logits + (size_t)r * Vv;

    float m = -1e30f, l = 0.f;
    for (int c = t; c < Vv; c += 256) {
        float x = lg[c];
        if (x > m) { l = l * __expf(m - x) + 1.f; m = x; }
        else       { l += __expf(x - m); }
    }
    sm[t] = m; sl[t] = l; __syncthreads();
    for (int o = 128; o > 0; o >>= 1) {
        if (t < o) {
            float m1 = sm[t], m2 = sm[t + o];
            float M = fmaxf(m1, m2);
            sl[t] = sl[t] * __expf(m1 - M) + sl[t + o] * __expf(m2 - M);
            sm[t] = M;
        }
        __syncthreads();
    }
    if (t == 0)
        rl[r] = (sm[0] + logf(sl[0])) - lg[tgt[r]];
}

__global__ __launch_bounds__(256)
void meanloss_kernel(const float* __restrict__ rl, float* __restrict__ out) {
    __shared__ float red[256];
    int t = threadIdx.x;
    float s = 0.f;
    for (int i = t; i < BT; i += 256) s += rl[i];
    red[t] = s; __syncthreads();
    for (int o = 128; o > 0; o >>= 1) { if (t < o) red[t] += red[t + o]; __syncthreads(); }
    if (t == 0) out[0] = red[0] / (float)BT;
}

// ---------------- launch ----------------
extern "C" void kernel_launch(void* const* d_in, const int* in_sizes, int n_in,
                              void* d_out, int out_size) {
    const int*   idx    = (const int*)  d_in[0];
    const int*   tgt    = (const int*)  d_in[1];
    const float* tok    = (const float*)d_in[2];
    const float* pos    = (const float*)d_in[3];
    const float* Wq     = (const float*)d_in[4];
    const float* Wk     = (const float*)d_in[5];
    const float* Wv     = (const float*)d_in[6];
    const float* ln1g   = (const float*)d_in[7];
    const float* ln1b   = (const float*)d_in[8];
    const float* W1     = (const float*)d_in[9];
    const float* b1     = (const float*)d_in[10];
    const float* W2     = (const float*)d_in[11];
    const float* b2     = (const float*)d_in[12];
    const float* ln2g   = (const float*)d_in[13];
    const float* ln2b   = (const float*)d_in[14];
    const float* headw  = (const float*)d_in[15];
    const float* headb  = (const float*)d_in[16];
    float* out = (float*)d_out;

    float *x, *x2, *q, *k, *v, *y, *ff1, *rl, *wpad;
    cudaGetSymbolAddress((void**)&x,    g_x);
    cudaGetSymbolAddress((void**)&x2,   g_x2);
    cudaGetSymbolAddress((void**)&q,    g_q);
    cudaGetSymbolAddress((void**)&k,    g_k);
    cudaGetSymbolAddress((void**)&v,    g_v);
    cudaGetSymbolAddress((void**)&y,    g_y);
    cudaGetSymbolAddress((void**)&ff1,  g_ff1);
    cudaGetSymbolAddress((void**)&rl,   g_rl);
    cudaGetSymbolAddress((void**)&wpad, g_wpad);

    cudaFuncSetAttribute(attn_kernel,
                         cudaFuncAttributeMaxDynamicSharedMemorySize, ATTN_SMEM);

    embed_kernel<<<BT, 256>>>(idx, tok, pos, x);
    padw_kernel<<<Dd, 256>>>(headw, wpad);

    dim3 gQKV(18, BT / 128);
    dim3 gD(Dd / 128, BT / 128);             // 6 x 32
    dim3 gF(FF / 128, BT / 128);             // 24 x 32
    dim3 gV(VP / 128, BT / 128);             // 393 x 32

    for (int l = 0; l < Ll; l++) {
        const float* wq = Wq + (size_t)l * Dd * Dd;
        const float* wk = Wk + (size_t)l * Dd * Dd;
        const float* wv = Wv + (size_t)l * Dd * Dd;
        const float* w1 = W1 + (size_t)l * Dd * FF;
        const float* w2 = W2 + (size_t)l * FF * Dd;

        qkv_kernel<<<gQKV, 256>>>(x, wq, wk, wv, q, k, v);

        attn_kernel<<<dim3(Tt / 64, Hh, Bb), 256, ATTN_SMEM>>>(q, k, v, y);

        ln_res_kernel<<<BT, 256>>>(y, x, ln1g + l * Dd, ln1b + l * Dd, x2);

        tgemm_kernel<2><<<gF, 256>>>(x2, w1, b1 + (size_t)l * FF, ff1, FF, Dd, FF);
        tgemm_kernel<1><<<gD, 256>>>(ff1, w2, b2 + (size_t)l * Dd, y, Dd, FF, Dd);

        ln_res_kernel<<<BT, 256>>>(y, x2, ln2g + l * Dd, ln2b + l * Dd, x);
    }

    // head: padded, pre-converted B with stride VP; stores guarded to N=Vv
    tgemm_kernel<1><<<gV, 256>>>(x, wpad, headb, out, Vv, Dd, VP);

    rowloss_kernel<<<BT, 256>>>(out, tgt, rl);
    meanloss_kernel<<<1, 256>>>(rl, out + (size_t)BT * Vv);
}